// round 16
// baseline (speedup 1.0000x reference)
#include <cuda_runtime.h>
#include <cuda_bf16.h>
#include <cstdint>

// ---------------------------------------------------------------------------
// Problem constants
// ---------------------------------------------------------------------------
#define NQ     75      // query images
#define NWAY   5
#define NC     640     // channels (K)
#define NHW    441     // descriptors per image
#define NSD    2205    // class descriptors per way (5 shots * 441)
#define MROWS  33075   // 75*441 packed query rows
#define MTILES 259     // ceil(33075/128)
#define MPAD   (MTILES * 128)   // 33152
#define SPAD   2304    // padded N per way (18 tiles of 128)
#define NT     18      // n-tiles of 128 total
#define NTH    9       // n-tiles per CTA (half split)
#define BK     64
#define KCH    (NC / BK)        // 10 k-chunks per n-tile
#define TOTCH  (NTH * KCH)      // 90 flattened chunks per CTA
#define SAS    72      // smem row stride in bf16 (64 + 8 pad, conflict-free ldmatrix)

// sim smem layout (dynamic): 3-stage A ring | 3-stage B ring | merge
#define STG_BYTES (128 * SAS * 2)              // 18432
#define SB_OFF    (3 * STG_BYTES)              // 55296
#define MERGE_OFF (6 * STG_BYTES)              // 110592
#define SMEM_TOTAL (MERGE_OFF + 128 * 2 * 3 * 4 + 64)   // 113728 (~111KB)

// convert smem: [640][33] f32 + partials + sinv
#define CV_PAD    33
#define CV_SF     (NC * CV_PAD)                 // floats
#define CV_SMEM   ((CV_SF + 8 * 32 + 32) * 4)   // 85632 B

// ---------------------------------------------------------------------------
// Scratch (device globals; no cudaMalloc allowed)
// ---------------------------------------------------------------------------
__device__ __align__(1024) __nv_bfloat16 d_q[(size_t)MPAD * NC];
__device__ __align__(1024) __nv_bfloat16 d_s[(size_t)NWAY * SPAD * NC];
__device__ float d_top3[(size_t)NWAY * 2 * MPAD * 3];   // per (w, half, row) top-3

// ---------------------------------------------------------------------------
// Helpers
// ---------------------------------------------------------------------------
__device__ __forceinline__ uint32_t smem_u32(const void* p) {
    uint32_t a;
    asm("{ .reg .u64 t; cvta.to.shared.u64 t, %1; cvt.u32.u64 %0, t; }"
        : "=r"(a) : "l"(p));
    return a;
}
__device__ __forceinline__ void cp16(uint32_t dst, const void* src) {
    asm volatile("cp.async.cg.shared.global [%0], [%1], 16;" :: "r"(dst), "l"(src));
}
#define CP_COMMIT() asm volatile("cp.async.commit_group;" ::: "memory")
#define CP_WAIT(n)  asm volatile("cp.async.wait_group %0;" :: "n"(n) : "memory")

__device__ __forceinline__ void ldsm_x4(uint32_t& r0, uint32_t& r1, uint32_t& r2,
                                        uint32_t& r3, uint32_t a) {
    asm volatile("ldmatrix.sync.aligned.m8n8.x4.shared.b16 {%0,%1,%2,%3}, [%4];"
                 : "=r"(r0), "=r"(r1), "=r"(r2), "=r"(r3) : "r"(a));
}
__device__ __forceinline__ void mma16816(float* c, uint32_t a0, uint32_t a1,
                                         uint32_t a2, uint32_t a3,
                                         uint32_t b0, uint32_t b1) {
    asm volatile(
        "mma.sync.aligned.m16n8k16.row.col.f32.bf16.bf16.f32 "
        "{%0,%1,%2,%3}, {%4,%5,%6,%7}, {%8,%9}, {%0,%1,%2,%3};"
        : "+f"(c[0]), "+f"(c[1]), "+f"(c[2]), "+f"(c[3])
        : "r"(a0), "r"(a1), "r"(a2), "r"(a3), "r"(b0), "r"(b1));
}
__device__ __forceinline__ void ins3(float v, float& a, float& b, float& c) {
    if (v > c) {
        if (v > a)      { c = b; b = a; a = v; }
        else if (v > b) { c = b; b = v; }
        else            { c = v; }
    }
}

// ---------------------------------------------------------------------------
// Kernel 1: single-pass L2-normalize + transpose + bf16 convert.
// One block per (image, 32-row slab). Slab buffered in smem; source read ONCE.
// 75*14 query blocks + 25*14 support blocks = 1400.
// ---------------------------------------------------------------------------
__global__ void __launch_bounds__(256) convert_kernel(const float* __restrict__ x1,
                                                      const float* __restrict__ x2) {
    extern __shared__ float cs[];
    float* sf   = cs;                 // [640][CV_PAD]
    float* part = cs + CV_SF;         // [8][32]
    float* sinv = part + 8 * 32;      // [32]

    int bid = blockIdx.x;
    const float* src;
    __nv_bfloat16* dst;
    int m0;
    if (bid < 1050) {
        int img = bid / 14; m0 = (bid % 14) * 32;
        src = x1 + (size_t)img * NC * NHW;
        dst = d_q + (size_t)img * NHW * NC;          // packed, no per-image pad
    } else {
        int sid = bid - 1050;
        int img = sid / 14; m0 = (sid % 14) * 32;
        int w = img / 5, sh = img % 5;
        src = x2 + (size_t)img * NC * NHW;
        dst = d_s + ((size_t)w * SPAD + (size_t)sh * NHW) * NC;
    }
    const int tid = threadIdx.x;

    // Load slab: src[c][m0+m] -> sf[c][m]; warp reads 32 consecutive m (coalesced)
    for (int i = tid; i < NC * 32; i += 256) {
        int c = i >> 5, m = i & 31;
        float v = (m0 + m < NHW) ? src[(size_t)c * NHW + m0 + m] : 0.f;
        sf[c * CV_PAD + m] = v;
    }
    __syncthreads();

    // Norm partials: thread (m = tid&31, cy = tid>>5) strides c by 8
    {
        int m = tid & 31, cy = tid >> 5;
        float a = 0.f;
        for (int c = cy; c < NC; c += 8) {
            float v = sf[c * CV_PAD + m];
            a = fmaf(v, v, a);
        }
        part[cy * 32 + m] = a;
    }
    __syncthreads();
    if (tid < 32) {
        float s = 0.f;
#pragma unroll
        for (int j = 0; j < 8; j++) s += part[j * 32 + tid];
        sinv[tid] = rsqrtf(s);
    }
    __syncthreads();

    // Write: thread (m = tid>>3, qt = tid&7) owns 80 cols of row m
    {
        int m = tid >> 3, qt = tid & 7;
        if (m0 + m < NHW) {
            float iv = sinv[m];
            __nv_bfloat16* drow = dst + (size_t)(m0 + m) * NC + qt * 80;
            for (int i0 = 0; i0 < 80; i0 += 8) {
                __nv_bfloat16 tmp[8];
#pragma unroll
                for (int j = 0; j < 8; j++)
                    tmp[j] = __float2bfloat16(sf[(qt * 80 + i0 + j) * CV_PAD + m] * iv);
                *(uint4*)(drow + i0) = *(uint4*)tmp;
            }
        }
    }
}

// ---------------------------------------------------------------------------
// Kernel 2: bf16 mma.sync GEMM + fused top-3.
// CTA = (mtile, w, nhalf). 128 threads = 2 warpM x 2 warpN, warp tile 64x64.
// 90-chunk stream, 3-stage cp.async ring, one sync per chunk.
// Last global n-tile (29 valid cols): warpN=1 skips all MMA, warpN=0 computes
// only nh<2 — saves ~4% of chip MMA work; masked fold keeps it exact.
// ---------------------------------------------------------------------------
__global__ void __launch_bounds__(128, 2) sim_kernel() {
    extern __shared__ char smem[];
    const uint32_t sbA = smem_u32(smem);
    const uint32_t sbB = sbA + SB_OFF;
    float (*smerge)[2][3] = (float(*)[2][3])(smem + MERGE_OFF);

    const int bid   = blockIdx.x;
    const int half  = bid & 1;
    const int rest  = bid >> 1;
    const int w     = rest % NWAY;
    const int mtile = rest / NWAY;
    const int tid   = threadIdx.x;
    const int wid   = tid >> 5;
    const int lane  = tid & 31;
    const int warpM = wid & 1;
    const int warpN = wid >> 1;
    const int g8    = lane >> 2;
    const int tig   = lane & 3;

    const __nv_bfloat16* Ab = d_q + (size_t)mtile * 128 * NC;
    const __nv_bfloat16* Bw = d_s + ((size_t)w * SPAD + (size_t)half * NTH * 128) * NC;

    // loader mapping: 1024 16B-vectors per array per chunk; 8 per thread per array
    const int lrow0 = tid >> 3;            // 0..15, step 16 per j
    const int lc8   = (tid & 7) * 8;       // col in bf16

    // ldmatrix coords
    const int arow = warpM * 64 + (lane & 15);
    const int acol = (lane >> 4) * 8;
    const int brow = warpN * 64 + ((lane >> 4) << 3) + (lane & 7);  // + nh*16
    const int bcol = ((lane >> 3) & 1) * 8;                          // + ks*16

    float t0[8], t1[8], t2[8];
#pragma unroll
    for (int s = 0; s < 8; s++) { t0[s] = t1[s] = t2[s] = -1e30f; }

    float acc[4][8][4];   // [mf][nf][frag]

    auto issue = [&](int g2) {
        if (g2 < TOTCH) {
            int nt2 = g2 / KCH, kc2 = g2 - nt2 * KCH;
            uint32_t so = (uint32_t)(g2 % 3) * STG_BYTES;
            const __nv_bfloat16* As = Ab + kc2 * BK;
            const __nv_bfloat16* Bs = Bw + (size_t)nt2 * 128 * NC + kc2 * BK;
            uint32_t sdst = so + (uint32_t)(lrow0 * SAS + lc8) * 2;
            const __nv_bfloat16* ag = As + (size_t)lrow0 * NC + lc8;
            const __nv_bfloat16* bg = Bs + (size_t)lrow0 * NC + lc8;
#pragma unroll
            for (int j = 0; j < 8; j++) {
                cp16(sbA + sdst, ag);
                cp16(sbB + sdst, bg);
                sdst += 16 * SAS * 2;
                ag += 16 * NC;
                bg += 16 * NC;
            }
        }
        CP_COMMIT();
    };

    issue(0);
    issue(1);

    for (int g = 0; g < TOTCH; g++) {
        const int ntl = g / KCH;               // local n-tile 0..8
        const int kc  = g - ntl * KCH;
        const uint32_t cso = (uint32_t)(g % 3) * STG_BYTES;
        const bool lastt = (half == 1) && (ntl == NTH - 1);   // global tile 17

        CP_WAIT(1);           // chunk g landed
        __syncthreads();      // everyone done with stage (g+2)%3
        issue(g + 2);

        if (kc == 0) {
#pragma unroll
            for (int mf = 0; mf < 4; mf++)
#pragma unroll
                for (int nf = 0; nf < 8; nf++)
#pragma unroll
                    for (int j = 0; j < 4; j++) acc[mf][nf][j] = 0.f;
        }

        if (!lastt) {
#pragma unroll
            for (int ks = 0; ks < 4; ks++) {
                uint32_t a0[4], a1[4], a2[4], a3[4];
#pragma unroll
                for (int mf = 0; mf < 4; mf++) {
                    uint32_t addr = sbA + cso +
                        (uint32_t)((arow + mf * 16) * SAS + ks * 16 + acol) * 2;
                    ldsm_x4(a0[mf], a1[mf], a2[mf], a3[mf], addr);
                }
                uint32_t b[8][2];
#pragma unroll
                for (int nh = 0; nh < 4; nh++) {
                    uint32_t addr = sbB + cso +
                        (uint32_t)((brow + nh * 16) * SAS + ks * 16 + bcol) * 2;
                    uint32_t r0, r1, r2, r3;
                    ldsm_x4(r0, r1, r2, r3, addr);
                    b[nh * 2][0] = r0;     b[nh * 2][1] = r1;
                    b[nh * 2 + 1][0] = r2; b[nh * 2 + 1][1] = r3;
                }
#pragma unroll
                for (int mf = 0; mf < 4; mf++)
#pragma unroll
                    for (int nf = 0; nf < 8; nf++)
                        mma16816(acc[mf][nf], a0[mf], a1[mf], a2[mf], a3[mf],
                                 b[nf][0], b[nf][1]);
            }
        } else if (warpN == 0) {
            // last tile: only cols 0..31 can be valid (29) -> nh 0..1, nf 0..3
#pragma unroll
            for (int ks = 0; ks < 4; ks++) {
                uint32_t a0[4], a1[4], a2[4], a3[4];
#pragma unroll
                for (int mf = 0; mf < 4; mf++) {
                    uint32_t addr = sbA + cso +
                        (uint32_t)((arow + mf * 16) * SAS + ks * 16 + acol) * 2;
                    ldsm_x4(a0[mf], a1[mf], a2[mf], a3[mf], addr);
                }
                uint32_t b[4][2];
#pragma unroll
                for (int nh = 0; nh < 2; nh++) {
                    uint32_t addr = sbB + cso +
                        (uint32_t)((brow + nh * 16) * SAS + ks * 16 + bcol) * 2;
                    uint32_t r0, r1, r2, r3;
                    ldsm_x4(r0, r1, r2, r3, addr);
                    b[nh * 2][0] = r0;     b[nh * 2][1] = r1;
                    b[nh * 2 + 1][0] = r2; b[nh * 2 + 1][1] = r3;
                }
#pragma unroll
                for (int mf = 0; mf < 4; mf++)
#pragma unroll
                    for (int nf = 0; nf < 4; nf++)
                        mma16816(acc[mf][nf], a0[mf], a1[mf], a2[mf], a3[mf],
                                 b[nf][0], b[nf][1]);
            }
        }

        if (kc == KCH - 1) {
            // fold this n-tile into running top-3 (mask N padding on last tile)
            const int ntg = half * NTH + ntl;  // global n-tile
            const int climit = (ntg == NT - 1) ? (NSD - (NT - 1) * 128) : 128;
#pragma unroll
            for (int mf = 0; mf < 4; mf++) {
                const int s0 = mf * 2, s1 = mf * 2 + 1;
#pragma unroll
                for (int nf = 0; nf < 8; nf++) {
                    const int colb = warpN * 64 + nf * 8 + tig * 2;
                    const bool u0 = colb < climit, u1 = colb + 1 < climit;
                    const float* c = acc[mf][nf];
                    if (u0) { ins3(c[0], t0[s0], t1[s0], t2[s0]);
                              ins3(c[2], t0[s1], t1[s1], t2[s1]); }
                    if (u1) { ins3(c[1], t0[s0], t1[s0], t2[s0]);
                              ins3(c[3], t0[s1], t1[s1], t2[s1]); }
                }
            }
        }
    }

    // intra-warp merge across the 4 lanes sharing each row
#pragma unroll
    for (int s = 0; s < 8; s++) {
#pragma unroll
        for (int d = 1; d <= 2; d <<= 1) {
            float m0 = __shfl_xor_sync(0xffffffffu, t0[s], d);
            float m1 = __shfl_xor_sync(0xffffffffu, t1[s], d);
            float m2 = __shfl_xor_sync(0xffffffffu, t2[s], d);
            ins3(m0, t0[s], t1[s], t2[s]);
            ins3(m1, t0[s], t1[s], t2[s]);
            ins3(m2, t0[s], t1[s], t2[s]);
        }
    }
    if (tig == 0) {
#pragma unroll
        for (int s = 0; s < 8; s++) {
            int row = warpM * 64 + (s >> 1) * 16 + (s & 1) * 8 + g8;
            smerge[row][warpN][0] = t0[s];
            smerge[row][warpN][1] = t1[s];
            smerge[row][warpN][2] = t2[s];
        }
    }
    __syncthreads();

    // merge the 2 N-warps per row; write per-row top-3 for this half
    {
        int grow = mtile * 128 + tid;
        if (grow < MROWS) {
            float a = smerge[tid][0][0], b = smerge[tid][0][1], c = smerge[tid][0][2];
            ins3(smerge[tid][1][0], a, b, c);
            ins3(smerge[tid][1][1], a, b, c);
            ins3(smerge[tid][1][2], a, b, c);
            float* dst = d_top3 + ((size_t)(w * 2 + half) * MPAD + grow) * 3;
            dst[0] = a; dst[1] = b; dst[2] = c;
        }
    }
}

// ---------------------------------------------------------------------------
// Kernel 3: one warp per (q, w): merge the two halves' top-3 per row, sum.
// ---------------------------------------------------------------------------
__global__ void reduce_kernel(float* __restrict__ out) {
    int wi = (blockIdx.x * blockDim.x + threadIdx.x) >> 5;
    int lane = threadIdx.x & 31;
    if (wi >= NQ * NWAY) return;
    int q = wi / NWAY, w = wi % NWAY;
    const float* h0 = d_top3 + ((size_t)(w * 2 + 0) * MPAD + (size_t)q * NHW) * 3;
    const float* h1 = d_top3 + ((size_t)(w * 2 + 1) * MPAD + (size_t)q * NHW) * 3;
    float s = 0.f;
    for (int m = lane; m < NHW; m += 32) {
        float a = h0[m * 3], b = h0[m * 3 + 1], c = h0[m * 3 + 2];
        ins3(h1[m * 3],     a, b, c);
        ins3(h1[m * 3 + 1], a, b, c);
        ins3(h1[m * 3 + 2], a, b, c);
        s += a + b + c;
    }
#pragma unroll
    for (int o = 16; o > 0; o >>= 1) s += __shfl_xor_sync(0xffffffffu, s, o);
    if (lane == 0) out[wi] = s;
}

// ---------------------------------------------------------------------------
extern "C" void kernel_launch(void* const* d_in, const int* in_sizes, int n_in,
                              void* d_out, int out_size) {
    const float* x1 = (const float*)d_in[0];   // [75, 640, 21, 21]
    const float* x2 = (const float*)d_in[1];   // [25, 640, 21, 21]
    float* out = (float*)d_out;                // [75, 5]

    cudaFuncSetAttribute(sim_kernel, cudaFuncAttributeMaxDynamicSharedMemorySize,
                         SMEM_TOTAL);
    cudaFuncSetAttribute(convert_kernel, cudaFuncAttributeMaxDynamicSharedMemorySize,
                         CV_SMEM);

    convert_kernel<<<1400, 256, CV_SMEM>>>(x1, x2);
    sim_kernel<<<MTILES * NWAY * 2, 128, SMEM_TOTAL>>>();
    reduce_kernel<<<(NQ * NWAY * 32 + 255) / 256, 256>>>(out);
}